// round 1
// baseline (speedup 1.0000x reference)
#include <cuda_runtime.h>
#include <math.h>

#define BB 16
#define NN 512
#define DD 12
#define HID 32
#define HEADS 4
#define CC 8
#define BN (BB*NN)        // 8192
#define NW (NN/32)        // 16 mask words per column

// ---------------- scratch (no allocs allowed) ----------------
__device__ float    d_g[BN*HID];          // g features         (1 MB)
__device__ float    d_as[BN*HEADS];       // a_src per node
__device__ float    d_ad[BN*HEADS];       // a_dst per node
__device__ float    d_hgnn[BN*HID];       // aggregated + bias  (1 MB)
__device__ float    d_tiT[HID*BN];        // ti transposed [h][bn] (b1 folded in)
__device__ float    d_tjT[HID*BN];        // tj transposed [h][bn]
__device__ unsigned d_maskT[BB*NN*NW];    // bit-packed (adj|eye) columns (512 KB)

// ---------------- kernel 1: node features --------------------
// h = relu(Wp x + bp); g = Wg h; a_s/a_d = <g, att>
__global__ void k1_features(const float* __restrict__ x,
                            const float* __restrict__ Wp,
                            const float* __restrict__ bp,
                            const float* __restrict__ Wg,
                            const float* __restrict__ att_src,
                            const float* __restrict__ att_dst) {
    __shared__ float sWp[HID*DD];
    __shared__ float sbp[HID];
    __shared__ float sWg[HID*HID];
    __shared__ float sas[HID];
    __shared__ float sad[HID];
    int t = threadIdx.x;
    for (int i = t; i < HID*DD;  i += blockDim.x) sWp[i] = Wp[i];
    for (int i = t; i < HID;     i += blockDim.x) sbp[i] = bp[i];
    for (int i = t; i < HID*HID; i += blockDim.x) sWg[i] = Wg[i];
    for (int i = t; i < HID;     i += blockDim.x) { sas[i] = att_src[i]; sad[i] = att_dst[i]; }
    __syncthreads();

    int n = blockIdx.x * blockDim.x + t;
    if (n >= BN) return;

    float xr[DD];
#pragma unroll
    for (int d = 0; d < DD; d++) xr[d] = x[n*DD + d];

    float h[HID];
#pragma unroll
    for (int k = 0; k < HID; k++) {
        float a = sbp[k];
#pragma unroll
        for (int d = 0; d < DD; d++) a = fmaf(xr[d], sWp[k*DD + d], a);
        h[k] = fmaxf(a, 0.f);
    }

    float as0=0,as1=0,as2=0,as3=0, ad0=0,ad1=0,ad2=0,ad3=0;
#pragma unroll
    for (int k = 0; k < HID; k++) {
        float a = 0.f;
#pragma unroll
        for (int d = 0; d < HID; d++) a = fmaf(h[d], sWg[k*HID + d], a);
        d_g[n*HID + k] = a;
        int hh = k >> 3;  // k / CC
        float vs = a * sas[k];
        float vd = a * sad[k];
        if (hh == 0) { as0 += vs; ad0 += vd; }
        else if (hh == 1) { as1 += vs; ad1 += vd; }
        else if (hh == 2) { as2 += vs; ad2 += vd; }
        else { as3 += vs; ad3 += vd; }
    }
    d_as[n*HEADS+0] = as0; d_as[n*HEADS+1] = as1; d_as[n*HEADS+2] = as2; d_as[n*HEADS+3] = as3;
    d_ad[n*HEADS+0] = ad0; d_ad[n*HEADS+1] = ad1; d_ad[n*HEADS+2] = ad2; d_ad[n*HEADS+3] = ad3;
}

// ---------------- kernel T: transpose + bit-pack softmax mask ----------------
// maskT[b][j][w] bit p  <->  (adj[b][32w+p][j] != 0) || (32w+p == j)
__global__ void kT_mask(const int* __restrict__ adj) {
    __shared__ int s[32][33];
    int b  = blockIdx.z;
    int i0 = blockIdx.y * 32;
    int j0 = blockIdx.x * 32;
    int tx = threadIdx.x, ty = threadIdx.y;
    s[ty][tx] = adj[((b*NN + i0 + ty)*NN) + j0 + tx];   // coalesced (tx = j)
    __syncthreads();
    // warp ty packs column j = j0+ty, lane tx = i bit
    int jl = ty;
    int i  = i0 + tx;
    int v  = s[tx][jl];
    bool m = (v != 0) || (i == (j0 + jl));
    unsigned w = __ballot_sync(0xffffffffu, m);
    if (tx == 0)
        d_maskT[(b*NN + j0 + jl)*NW + (i0 >> 5)] = w;
}

// ---------------- kernel 2: masked attention + aggregation ----------------
// h_gnn[b,j,h,c] = (sum_i m * exp(lrelu(a_s[i,h]+a_d[j,h])) * g[i,h,c]) / denom + bias
// logits are tiny (|l| < ~1), so no max-subtraction is needed (exact same softmax).
#define JT 32
__global__ void k2_attn(const float* __restrict__ bias_g) {
    __shared__ float4   sg4[256*8];        // half of g for this batch: 32 KB
    __shared__ float    sas[NN*HEADS];     // 8 KB
    __shared__ unsigned smask[JT*17];      // padded 16->17 to kill bank conflicts
    __shared__ float    sbias[HID];

    int b  = blockIdx.y;
    int j0 = blockIdx.x * JT;
    int t  = threadIdx.x;            // 128 threads: warp = head, lane = j
    int h  = t >> 5;
    int jl = t & 31;
    int base = b * NN;

    for (int k = t; k < NN*HEADS; k += 128) sas[k] = d_as[base*HEADS + k];
    for (int k = t; k < JT*NW; k += 128) {
        int r = k / NW, c = k % NW;
        smask[r*17 + c] = d_maskT[(base + j0)*NW + k];
    }
    if (t < HID) sbias[t] = bias_g[t];

    int j = j0 + jl;
    float adv = d_ad[(base + j)*HEADS + h];

    float acc0=0,acc1=0,acc2=0,acc3=0,acc4=0,acc5=0,acc6=0,acc7=0,den=0;

    for (int half = 0; half < 2; half++) {
        const float4* gg = (const float4*)(d_g + (base + half*256)*HID);
        __syncthreads();   // protect sg4 from previous iteration readers
        for (int k = t; k < 256*8; k += 128) sg4[k] = gg[k];
        __syncthreads();

#pragma unroll 1
        for (int iw = 0; iw < 8; iw++) {
            unsigned w = smask[jl*17 + half*8 + iw];
#pragma unroll
            for (int ib = 0; ib < 32; ib++) {
                int il = iw*32 + ib;                       // local i in [0,256)
                float l  = sas[(half*256 + il)*HEADS + h] + adv;
                float lr = fmaxf(l, 0.2f*l);               // leaky_relu(l, 0.2)
                float e  = ((w >> ib) & 1u) ? __expf(lr) : 0.f;
                den += e;
                float4 ga = sg4[il*8 + h*2];
                float4 gb = sg4[il*8 + h*2 + 1];
                acc0 = fmaf(e, ga.x, acc0); acc1 = fmaf(e, ga.y, acc1);
                acc2 = fmaf(e, ga.z, acc2); acc3 = fmaf(e, ga.w, acc3);
                acc4 = fmaf(e, gb.x, acc4); acc5 = fmaf(e, gb.y, acc5);
                acc6 = fmaf(e, gb.z, acc6); acc7 = fmaf(e, gb.w, acc7);
            }
        }
    }

    float inv = 1.f / den;   // diagonal always in mask -> den > 0
    float* o = &d_hgnn[(base + j)*HID + h*CC];
    float4 o0 = make_float4(fmaf(acc0,inv,sbias[h*CC+0]), fmaf(acc1,inv,sbias[h*CC+1]),
                            fmaf(acc2,inv,sbias[h*CC+2]), fmaf(acc3,inv,sbias[h*CC+3]));
    float4 o1 = make_float4(fmaf(acc4,inv,sbias[h*CC+4]), fmaf(acc5,inv,sbias[h*CC+5]),
                            fmaf(acc6,inv,sbias[h*CC+6]), fmaf(acc7,inv,sbias[h*CC+7]));
    ((float4*)o)[0] = o0;
    ((float4*)o)[1] = o1;
}

// ---------------- kernel 3: ti/tj projections (transposed, b1 folded) ----------------
__global__ void k3_titj(const float* __restrict__ W1, const float* __restrict__ b1) {
    __shared__ float sW1[HID*2*HID];   // 8 KB
    __shared__ float sb1[HID];
    __shared__ float shg[128*33];      // padded rows

    int t  = threadIdx.x;              // 128 threads
    int n0 = blockIdx.x * 128;
    for (int i = t; i < HID*2*HID; i += 128) sW1[i] = W1[i];
    if (t < HID) sb1[t] = b1[t];
    for (int k = t; k < 128*HID; k += 128) {
        int r = k >> 5, c = k & 31;
        shg[r*33 + c] = d_hgnn[n0*HID + k];
    }
    __syncthreads();

    int n = n0 + t;
    float hg[HID];
#pragma unroll
    for (int d = 0; d < HID; d++) hg[d] = shg[t*33 + d];

#pragma unroll 4
    for (int hh = 0; hh < HID; hh++) {
        float ti = sb1[hh], tj = 0.f;
#pragma unroll
        for (int d = 0; d < HID; d++) {
            ti = fmaf(hg[d], sW1[hh*64 + d],      ti);
            tj = fmaf(hg[d], sW1[hh*64 + 32 + d], tj);
        }
        d_tiT[hh*BN + n] = ti;
        d_tjT[hh*BN + n] = tj;
    }
}

// ---------------- kernel 4: pairwise score (dominant kernel) ----------------
// out[b,i,j] = (adj && i!=j) ? sigmoid(sum_h relu(ti[i,h]+tj[j,h])*w2[h] + b2) : 0
#define IT 32
__global__ void __launch_bounds__(512) k4_score(const int* __restrict__ adj,
                                                const float* __restrict__ w2,
                                                const float* __restrict__ b2p,
                                                float* __restrict__ out) {
    __shared__ float4 sti[IT*HID/4];   // [ii][h] as float4, 4 KB
    __shared__ float  sw2[HID];

    int b  = blockIdx.y;
    int i0 = blockIdx.x * IT;
    int t  = threadIdx.x;              // 512 threads, one j each

    for (int k = t; k < IT*HID; k += 512) {
        int ii = k >> 5, hh = k & 31;
        ((float*)sti)[ii*HID + hh] = d_tiT[hh*BN + b*NN + i0 + ii];
    }
    if (t < HID) sw2[t] = w2[t];
    __syncthreads();

    int j = t;
    float b2v = b2p[0];

    float tj[HID];
#pragma unroll
    for (int hh = 0; hh < HID; hh++) tj[hh] = d_tjT[hh*BN + b*NN + j];

    float4 w4[HID/4];
#pragma unroll
    for (int k = 0; k < HID/4; k++) w4[k] = ((const float4*)sw2)[k];

    const int* arow = adj + (b*NN + i0)*NN + j;
    float*     orow = out + (size_t)(b*NN + i0)*NN + j;

#pragma unroll 1
    for (int ii = 0; ii < IT; ii++) {
        int av = arow[ii*NN];
        float acc = b2v;
#pragma unroll
        for (int k = 0; k < HID/4; k++) {
            float4 t4 = sti[ii*8 + k];
            acc = fmaf(fmaxf(t4.x + tj[4*k+0], 0.f), w4[k].x, acc);
            acc = fmaf(fmaxf(t4.y + tj[4*k+1], 0.f), w4[k].y, acc);
            acc = fmaf(fmaxf(t4.z + tj[4*k+2], 0.f), w4[k].z, acc);
            acc = fmaf(fmaxf(t4.w + tj[4*k+3], 0.f), w4[k].w, acc);
        }
        float s = 1.f / (1.f + __expf(-acc));
        bool on = (av != 0) && ((i0 + ii) != j);
        orow[ii*NN] = on ? s : 0.f;
    }
}

// ---------------- launcher ----------------
extern "C" void kernel_launch(void* const* d_in, const int* in_sizes, int n_in,
                              void* d_out, int out_size) {
    const float* x       = (const float*)d_in[0];
    const int*   adj     = (const int*)  d_in[1];
    const float* Wp      = (const float*)d_in[2];
    const float* bp      = (const float*)d_in[3];
    const float* Wg      = (const float*)d_in[4];
    const float* att_src = (const float*)d_in[5];
    const float* att_dst = (const float*)d_in[6];
    const float* bias_g  = (const float*)d_in[7];
    const float* W1      = (const float*)d_in[8];
    const float* b1      = (const float*)d_in[9];
    const float* w2      = (const float*)d_in[10];
    const float* b2      = (const float*)d_in[11];
    float* out = (float*)d_out;

    k1_features<<<BN/128, 128>>>(x, Wp, bp, Wg, att_src, att_dst);
    kT_mask<<<dim3(NN/32, NN/32, BB), dim3(32, 32)>>>(adj);
    k2_attn<<<dim3(NN/JT, BB), 128>>>(bias_g);
    k3_titj<<<BN/128, 128>>>(W1, b1);
    k4_score<<<dim3(NN/IT, BB), 512>>>(adj, w2, b2, out);
}

// round 2
// speedup vs baseline: 1.4407x; 1.4407x over previous
#include <cuda_runtime.h>
#include <math.h>
#include <string.h>

#define BB 16
#define NN 512
#define DD 12
#define HID 32
#define HEADS 4
#define CC 8
#define BN (BB*NN)        // 8192
#define NW (NN/32)        // 16 mask words per column

// ---------------- scratch (no allocs allowed) ----------------
__device__ float    d_g[BN*HID];          // g features         (1 MB)
__device__ float    d_as[BN*HEADS];       // a_src per node
__device__ float    d_ad[BN*HEADS];       // a_dst per node
__device__ float    d_tiT[HID*BN];        // ti transposed [h][bn] (b1 folded in)
__device__ float    d_tjT[HID*BN];        // tj transposed [h][bn]
__device__ unsigned d_maskT[BB*NN*NW];    // bit-packed (adj|eye) columns (512 KB)

// ---------------- packed f32x2 helpers (sm_103a FFMA2 path) ----------------
__device__ __forceinline__ unsigned long long f2u(float2 v) {
    unsigned long long u; memcpy(&u, &v, 8); return u;
}
__device__ __forceinline__ float2 u2f(unsigned long long u) {
    float2 v; memcpy(&v, &u, 8); return v;
}
__device__ __forceinline__ float2 ffma2(float2 a, float2 b, float2 c) {
    unsigned long long d;
    asm("fma.rn.f32x2 %0, %1, %2, %3;" : "=l"(d) : "l"(f2u(a)), "l"(f2u(b)), "l"(f2u(c)));
    return u2f(d);
}
__device__ __forceinline__ float2 fadd2(float2 a, float2 b) {
    unsigned long long d;
    asm("add.rn.f32x2 %0, %1, %2;" : "=l"(d) : "l"(f2u(a)), "l"(f2u(b)));
    return u2f(d);
}

// ---------------- kernel 1: node features --------------------
// thread = (n, head-quarter): 4 threads per node -> 256 blocks of 128
__global__ void k1_features(const float* __restrict__ x,
                            const float* __restrict__ Wp,
                            const float* __restrict__ bp,
                            const float* __restrict__ Wg,
                            const float* __restrict__ att_src,
                            const float* __restrict__ att_dst) {
    __shared__ float sWp[HID*DD];
    __shared__ float sbp[HID];
    __shared__ float sWg[HID*HID];
    __shared__ float sas[HID];
    __shared__ float sad[HID];
    int t = threadIdx.x;
    for (int i = t; i < HID*DD;  i += blockDim.x) sWp[i] = Wp[i];
    for (int i = t; i < HID;     i += blockDim.x) sbp[i] = bp[i];
    for (int i = t; i < HID*HID; i += blockDim.x) sWg[i] = Wg[i];
    for (int i = t; i < HID;     i += blockDim.x) { sas[i] = att_src[i]; sad[i] = att_dst[i]; }
    __syncthreads();

    int idx = blockIdx.x * blockDim.x + t;    // 0..32767
    int n = idx >> 2;
    int q = idx & 3;                           // head / k-quarter

    float xr[DD];
#pragma unroll
    for (int d = 0; d < DD; d++) xr[d] = x[n*DD + d];

    float h[HID];
#pragma unroll
    for (int k = 0; k < HID; k++) {
        float a = sbp[k];
#pragma unroll
        for (int d = 0; d < DD; d++) a = fmaf(xr[d], sWp[k*DD + d], a);
        h[k] = fmaxf(a, 0.f);
    }

    float gg[CC];
    float asv = 0.f, adv = 0.f;
#pragma unroll
    for (int c = 0; c < CC; c++) {
        int k = q*CC + c;
        float a = 0.f;
#pragma unroll
        for (int d = 0; d < HID; d++) a = fmaf(h[d], sWg[k*HID + d], a);
        gg[c] = a;
        asv = fmaf(a, sas[k], asv);
        adv = fmaf(a, sad[k], adv);
    }
    float4* go = (float4*)&d_g[n*HID + q*CC];
    go[0] = make_float4(gg[0], gg[1], gg[2], gg[3]);
    go[1] = make_float4(gg[4], gg[5], gg[6], gg[7]);
    d_as[n*HEADS + q] = asv;
    d_ad[n*HEADS + q] = adv;
}

// ---------------- kernel T: transpose + bit-pack softmax mask ----------------
// maskT[b][j][w] bit p  <->  (adj[b][32w+p][j] != 0) || (32w+p == j)
__global__ void kT_mask(const int* __restrict__ adj) {
    __shared__ int s[32][33];
    int b  = blockIdx.z;
    int i0 = blockIdx.y * 32;
    int j0 = blockIdx.x * 32;
    int tx = threadIdx.x, ty = threadIdx.y;
    s[ty][tx] = adj[((b*NN + i0 + ty)*NN) + j0 + tx];   // coalesced (tx = j)
    __syncthreads();
    int jl = ty;
    int i  = i0 + tx;
    int v  = s[tx][jl];
    bool m = (v != 0) || (i == (j0 + jl));
    unsigned w = __ballot_sync(0xffffffffu, m);
    if (tx == 0)
        d_maskT[(b*NN + j0 + jl)*NW + (i0 >> 5)] = w;
}

// ---------------- kernel 2: masked attention + aggregation + fused ti/tj ----------------
// 256 threads: group (t>>7) splits the i-range; (h, jl) = ((t>>5)&3, t&31).
#define JT 32
__global__ void __launch_bounds__(256) k2_attn(const float* __restrict__ bias_g,
                                               const float* __restrict__ W1,
                                               const float* __restrict__ b1) {
    __shared__ float4   sg4[256*8];        // 32 KB; aliased by sred/shg/sW1 after use
    __shared__ float    sas[NN*HEADS];     // 8 KB
    __shared__ unsigned smask[JT*17];      // padded to kill bank conflicts
    __shared__ float    sbias[HID];
    __shared__ float    sb1[HID];

    float* salias = (float*)sg4;
    float* sred = salias;                  // [128][10]  (grp1 partials)
    float* shg  = salias + 2048;           // [32][33]   (h_gnn for 32 nodes)
    float* sW1  = salias + 4096;           // [2048]

    int b  = blockIdx.y;
    int j0 = blockIdx.x * JT;
    int t  = threadIdx.x;
    int grp = t >> 7;
    int wt  = t & 127;
    int h   = wt >> 5;
    int jl  = wt & 31;
    int base = b * NN;

    for (int k = t; k < NN*HEADS; k += 256) sas[k] = d_as[base*HEADS + k];
    for (int k = t; k < JT*NW; k += 256) {
        int r = k / NW, c = k % NW;
        smask[r*17 + c] = d_maskT[(base + j0)*NW + k];
    }
    if (t < HID) sbias[t] = bias_g[t];
    else if (t < 2*HID) sb1[t - HID] = b1[t - HID];

    int j = j0 + jl;
    float adv = d_ad[(base + j)*HEADS + h];

    float2 a01 = {0,0}, a23 = {0,0}, a45 = {0,0}, a67 = {0,0};
    float den = 0.f;

    for (int half = 0; half < 2; half++) {
        const float4* gg = (const float4*)(d_g + (base + half*256)*HID);
        __syncthreads();
        for (int k = t; k < 256*8; k += 256) sg4[k] = gg[k];
        __syncthreads();

#pragma unroll 1
        for (int iw2 = 0; iw2 < 4; iw2++) {
            int iw = grp*4 + iw2;
            unsigned w = smask[jl*17 + half*8 + iw];
#pragma unroll
            for (int ib = 0; ib < 32; ib++) {
                int il = iw*32 + ib;
                float l  = sas[(half*256 + il)*HEADS + h] + adv;
                float lr = fmaxf(l, 0.2f*l);
                float e  = ((w >> ib) & 1u) ? __expf(lr) : 0.f;
                den += e;
                float2 e2 = make_float2(e, e);
                float4 ga = sg4[il*8 + h*2];
                float4 gb = sg4[il*8 + h*2 + 1];
                a01 = ffma2(e2, make_float2(ga.x, ga.y), a01);
                a23 = ffma2(e2, make_float2(ga.z, ga.w), a23);
                a45 = ffma2(e2, make_float2(gb.x, gb.y), a45);
                a67 = ffma2(e2, make_float2(gb.z, gb.w), a67);
            }
        }
    }

    __syncthreads();                 // all reads of sg4 done; alias region live
    if (grp == 1) {
        float* r = sred + wt*10;
        r[0]=a01.x; r[1]=a01.y; r[2]=a23.x; r[3]=a23.y;
        r[4]=a45.x; r[5]=a45.y; r[6]=a67.x; r[7]=a67.y; r[8]=den;
    }
    for (int k = t; k < HID*2*HID; k += 256) sW1[k] = W1[k];
    __syncthreads();
    if (grp == 0) {
        float* r = sred + wt*10;
        a01.x+=r[0]; a01.y+=r[1]; a23.x+=r[2]; a23.y+=r[3];
        a45.x+=r[4]; a45.y+=r[5]; a67.x+=r[6]; a67.y+=r[7]; den+=r[8];
        float inv = 1.f / den;       // diagonal always in mask
        float* o = shg + jl*33 + h*CC;
        o[0]=fmaf(a01.x,inv,sbias[h*CC+0]); o[1]=fmaf(a01.y,inv,sbias[h*CC+1]);
        o[2]=fmaf(a23.x,inv,sbias[h*CC+2]); o[3]=fmaf(a23.y,inv,sbias[h*CC+3]);
        o[4]=fmaf(a45.x,inv,sbias[h*CC+4]); o[5]=fmaf(a45.y,inv,sbias[h*CC+5]);
        o[6]=fmaf(a67.x,inv,sbias[h*CC+6]); o[7]=fmaf(a67.y,inv,sbias[h*CC+7]);
    }
    __syncthreads();

    // fused ti/tj: 2048 outputs (1024 ti, 1024 tj), 256 threads -> 8 each
#pragma unroll
    for (int rep = 0; rep < 8; rep++) {
        int o = rep*256 + t;
        int is_tj = o >> 10;
        int hh = (o >> 5) & 31;
        int nl = o & 31;
        float acc = is_tj ? 0.f : sb1[hh];
        const float* wrow = sW1 + hh*64 + is_tj*32;
        const float* hr = shg + nl*33;
#pragma unroll
        for (int d = 0; d < HID; d++) acc = fmaf(hr[d], wrow[d], acc);
        float* dst = is_tj ? d_tjT : d_tiT;
        dst[hh*BN + base + j0 + nl] = acc;
    }
}

// ---------------- kernel 4: pairwise score (dominant kernel) ----------------
// out[b,i,j] = (adj && i!=j) ? sigmoid(sum_h relu(ti[i,h]+tj[j,h])*w2[h] + b2) : 0
// mask derived from d_maskT: for i!=j, (adj|eye) == adj.
#define IT 32
__global__ void __launch_bounds__(512) k4_score(const float* __restrict__ w2,
                                                const float* __restrict__ b2p,
                                                float* __restrict__ out) {
    __shared__ float sti[IT*36];   // [ii][hh], pad 36 keeps float2 alignment
    __shared__ float sw2[HID];

    int b  = blockIdx.y;
    int i0 = blockIdx.x * IT;
    int t  = threadIdx.x;          // 512 threads, one j each
    int base = b * NN;

    for (int k = t; k < IT*HID; k += 512) {
        int hh = k >> 5, ii = k & 31;            // ii fast -> coalesced gmem
        sti[ii*36 + hh] = d_tiT[hh*BN + base + i0 + ii];
    }
    if (t < HID) sw2[t] = w2[t];
    __syncthreads();

    int j = t;
    float b2v = b2p[0];

    float2 tj2[HID/2];
#pragma unroll
    for (int k = 0; k < HID/2; k++)
        tj2[k] = make_float2(d_tjT[(2*k)*BN + base + j], d_tjT[(2*k+1)*BN + base + j]);

    float2 w22[HID/2];
#pragma unroll
    for (int k = 0; k < HID/2; k++) w22[k] = ((const float2*)sw2)[k];

    unsigned mw = d_maskT[(base + j)*NW + (i0 >> 5)];
    float* orow = out + (size_t)(base + i0)*NN + j;

#pragma unroll 2
    for (int ii = 0; ii < IT; ii++) {
        const float* tip = sti + ii*36;
        float2 a0 = {0,0}, a1 = {0,0}, a2 = {0,0}, a3 = {0,0};
#pragma unroll
        for (int k = 0; k < HID/2; k += 4) {
            float2 u;
            u = fadd2(((const float2*)tip)[k+0], tj2[k+0]);
            u.x = fmaxf(u.x, 0.f); u.y = fmaxf(u.y, 0.f);
            a0 = ffma2(u, w22[k+0], a0);
            u = fadd2(((const float2*)tip)[k+1], tj2[k+1]);
            u.x = fmaxf(u.x, 0.f); u.y = fmaxf(u.y, 0.f);
            a1 = ffma2(u, w22[k+1], a1);
            u = fadd2(((const float2*)tip)[k+2], tj2[k+2]);
            u.x = fmaxf(u.x, 0.f); u.y = fmaxf(u.y, 0.f);
            a2 = ffma2(u, w22[k+2], a2);
            u = fadd2(((const float2*)tip)[k+3], tj2[k+3]);
            u.x = fmaxf(u.x, 0.f); u.y = fmaxf(u.y, 0.f);
            a3 = ffma2(u, w22[k+3], a3);
        }
        float2 sp = fadd2(fadd2(a0, a1), fadd2(a2, a3));
        float acc = sp.x + sp.y + b2v;
        float s = 1.f / (1.f + __expf(-acc));
        bool on = ((mw >> ii) & 1u) && ((i0 + ii) != j);
        orow[ii*NN] = on ? s : 0.f;
    }
}

// ---------------- launcher ----------------
extern "C" void kernel_launch(void* const* d_in, const int* in_sizes, int n_in,
                              void* d_out, int out_size) {
    const float* x       = (const float*)d_in[0];
    const int*   adj     = (const int*)  d_in[1];
    const float* Wp      = (const float*)d_in[2];
    const float* bp      = (const float*)d_in[3];
    const float* Wg      = (const float*)d_in[4];
    const float* att_src = (const float*)d_in[5];
    const float* att_dst = (const float*)d_in[6];
    const float* bias_g  = (const float*)d_in[7];
    const float* W1      = (const float*)d_in[8];
    const float* b1      = (const float*)d_in[9];
    const float* w2      = (const float*)d_in[10];
    const float* b2      = (const float*)d_in[11];
    float* out = (float*)d_out;

    k1_features<<<(BN*4)/128, 128>>>(x, Wp, bp, Wg, att_src, att_dst);
    kT_mask<<<dim3(NN/32, NN/32, BB), dim3(32, 32)>>>(adj);
    k2_attn<<<dim3(NN/JT, BB), 256>>>(bias_g, W1, b1);
    k4_score<<<dim3(NN/IT, BB), 512>>>(w2, b2, out);
}

// round 5
// speedup vs baseline: 1.8473x; 1.2822x over previous
#include <cuda_runtime.h>
#include <cuda_fp16.h>
#include <math.h>
#include <string.h>

#define BB 16
#define NN 512
#define DD 12
#define HID 32
#define HEADS 4
#define CC 8
#define BN (BB*NN)        // 8192
#define NW (NN/32)        // 16 mask words per column

// ---------------- scratch (no allocs allowed) ----------------
__device__ float    d_g[BN*HID];          // g features (1 MB)
__device__ float2   d_e12[BN*HEADS];      // (e^{as}, e^{0.2 as}) per (node, head)
__device__ float    d_ad[BN*HEADS];       // a_dst per node
__device__ __half2  d_tiH2[(HID/2)*BN];   // ti (b1 folded), half2 packed by h-pair
__device__ __half2  d_tjH2[(HID/2)*BN];   // tj, half2 packed by h-pair
__device__ unsigned d_maskT[BB*NN*NW];    // bit-packed (adj|eye) columns

// ---------------- packed f32x2 helpers ----------------
__device__ __forceinline__ unsigned long long f2u(float2 v) {
    unsigned long long u; memcpy(&u, &v, 8); return u;
}
__device__ __forceinline__ float2 u2f(unsigned long long u) {
    float2 v; memcpy(&v, &u, 8); return v;
}
__device__ __forceinline__ float2 ffma2(float2 a, float2 b, float2 c) {
    unsigned long long d;
    asm("fma.rn.f32x2 %0, %1, %2, %3;" : "=l"(d) : "l"(f2u(a)), "l"(f2u(b)), "l"(f2u(c)));
    return u2f(d);
}

// ---------------- kernel 1: node features --------------------
// thread = (n, head): 4 threads per node
__global__ void k1_features(const float* __restrict__ x,
                            const float* __restrict__ Wp,
                            const float* __restrict__ bp,
                            const float* __restrict__ Wg,
                            const float* __restrict__ att_src,
                            const float* __restrict__ att_dst) {
    __shared__ float sWp[HID*DD];
    __shared__ float sbp[HID];
    __shared__ float sWg[HID*HID];
    __shared__ float sas[HID];
    __shared__ float sad[HID];
    int t = threadIdx.x;
    for (int i = t; i < HID*DD;  i += blockDim.x) sWp[i] = Wp[i];
    for (int i = t; i < HID;     i += blockDim.x) sbp[i] = bp[i];
    for (int i = t; i < HID*HID; i += blockDim.x) sWg[i] = Wg[i];
    for (int i = t; i < HID;     i += blockDim.x) { sas[i] = att_src[i]; sad[i] = att_dst[i]; }
    __syncthreads();

    int idx = blockIdx.x * blockDim.x + t;
    int n = idx >> 2;
    int q = idx & 3;

    float xr[DD];
#pragma unroll
    for (int d = 0; d < DD; d++) xr[d] = x[n*DD + d];

    float h[HID];
#pragma unroll
    for (int k = 0; k < HID; k++) {
        float a = sbp[k];
#pragma unroll
        for (int d = 0; d < DD; d++) a = fmaf(xr[d], sWp[k*DD + d], a);
        h[k] = fmaxf(a, 0.f);
    }

    float gg[CC];
    float asv = 0.f, adv = 0.f;
#pragma unroll
    for (int c = 0; c < CC; c++) {
        int k = q*CC + c;
        float a = 0.f;
#pragma unroll
        for (int d = 0; d < HID; d++) a = fmaf(h[d], sWg[k*HID + d], a);
        gg[c] = a;
        asv = fmaf(a, sas[k], asv);
        adv = fmaf(a, sad[k], adv);
    }
    float4* go = (float4*)&d_g[n*HID + q*CC];
    go[0] = make_float4(gg[0], gg[1], gg[2], gg[3]);
    go[1] = make_float4(gg[4], gg[5], gg[6], gg[7]);
    d_e12[n*HEADS + q] = make_float2(__expf(asv), __expf(0.2f*asv));
    d_ad[n*HEADS + q] = adv;
}

// ---------------- kernel T: transpose + bit-pack softmax mask ----------------
__global__ void kT_mask(const int* __restrict__ adj) {
    __shared__ int s[32][33];
    int b  = blockIdx.z;
    int i0 = blockIdx.y * 32;
    int j0 = blockIdx.x * 32;
    int tx = threadIdx.x, ty = threadIdx.y;
    s[ty][tx] = adj[((b*NN + i0 + ty)*NN) + j0 + tx];
    __syncthreads();
    int jl = ty;
    int i  = i0 + tx;
    int v  = s[tx][jl];
    bool m = (v != 0) || (i == (j0 + jl));
    unsigned w = __ballot_sync(0xffffffffu, m);
    if (tx == 0)
        d_maskT[(b*NN + j0 + jl)*NW + (i0 >> 5)] = w;
}

// ---------------- kernel 2: attention + aggregation + fused ti/tj (half2 out) ----------------
#define JT 32
__global__ void __launch_bounds__(256) k2_attn(const float* __restrict__ bias_g,
                                               const float* __restrict__ W1,
                                               const float* __restrict__ b1) {
    __shared__ float4   sg4[256*8];        // 32 KB; aliased later
    __shared__ float2   sE[256*HEADS];     // 8 KB: (e^{as}, e^{0.2as}) for current half
    __shared__ unsigned smask[JT*17];
    __shared__ float    sbias[HID];
    __shared__ float    sb1[HID];

    float* salias = (float*)sg4;
    float* sred  = salias;                 // [128][10]
    float* shg   = salias + 2048;          // [32][33]
    float* sW1   = salias + 4096;          // [2048]
    float* sprod = salias + 6144;          // [2 side][32 hh][32 nl]

    int b  = blockIdx.y;
    int j0 = blockIdx.x * JT;
    int t  = threadIdx.x;
    int grp = t >> 7;
    int wt  = t & 127;
    int h   = wt >> 5;
    int jl  = wt & 31;
    int base = b * NN;

    for (int k = t; k < JT*NW; k += 256) {
        int r = k / NW, c = k % NW;
        smask[r*17 + c] = d_maskT[(base + j0)*NW + k];
    }
    if (t < HID) sbias[t] = bias_g[t];
    else if (t < 2*HID) sb1[t - HID] = b1[t - HID];

    int j = j0 + jl;
    float adv = d_ad[(base + j)*HEADS + h];
    float Ed1 = __expf(adv);
    float Ed2 = __expf(0.2f*adv);

    float2 a01 = {0,0}, a23 = {0,0}, a45 = {0,0}, a67 = {0,0};
    float den = 0.f;

    for (int half = 0; half < 2; half++) {
        const float4* gg = (const float4*)(d_g + (base + half*256)*HID);
        const float2* ee = d_e12 + (base + half*256)*HEADS;
        __syncthreads();
        for (int k = t; k < 256*8; k += 256) sg4[k] = gg[k];
        for (int k = t; k < 256*HEADS; k += 256) sE[k] = ee[k];
        __syncthreads();

#pragma unroll 1
        for (int iw2 = 0; iw2 < 4; iw2++) {
            int iw = grp*4 + iw2;
            unsigned w = smask[jl*17 + half*8 + iw];
#pragma unroll
            for (int ib = 0; ib < 32; ib++) {
                int il = iw*32 + ib;
                float2 E = sE[il*HEADS + h];
                float f1 = E.x * Ed1;
                float f2 = E.y * Ed2;
                float e0 = (f1 > 1.0f) ? f1 : f2;
                float e  = ((w >> ib) & 1u) ? e0 : 0.f;
                den += e;
                float2 e2 = make_float2(e, e);
                float4 ga = sg4[il*8 + h*2];
                float4 gb = sg4[il*8 + h*2 + 1];
                a01 = ffma2(e2, make_float2(ga.x, ga.y), a01);
                a23 = ffma2(e2, make_float2(ga.z, ga.w), a23);
                a45 = ffma2(e2, make_float2(gb.x, gb.y), a45);
                a67 = ffma2(e2, make_float2(gb.z, gb.w), a67);
            }
        }
    }

    __syncthreads();                 // sg4 reads done; alias region live
    if (grp == 1) {
        float* r = sred + wt*10;
        r[0]=a01.x; r[1]=a01.y; r[2]=a23.x; r[3]=a23.y;
        r[4]=a45.x; r[5]=a45.y; r[6]=a67.x; r[7]=a67.y; r[8]=den;
    }
    for (int k = t; k < HID*2*HID; k += 256) sW1[k] = W1[k];
    __syncthreads();
    if (grp == 0) {
        float* r = sred + wt*10;
        a01.x+=r[0]; a01.y+=r[1]; a23.x+=r[2]; a23.y+=r[3];
        a45.x+=r[4]; a45.y+=r[5]; a67.x+=r[6]; a67.y+=r[7]; den+=r[8];
        float inv = 1.f / den;       // diagonal always in mask
        float* o = shg + jl*33 + h*CC;
        o[0]=fmaf(a01.x,inv,sbias[h*CC+0]); o[1]=fmaf(a01.y,inv,sbias[h*CC+1]);
        o[2]=fmaf(a23.x,inv,sbias[h*CC+2]); o[3]=fmaf(a23.y,inv,sbias[h*CC+3]);
        o[4]=fmaf(a45.x,inv,sbias[h*CC+4]); o[5]=fmaf(a45.y,inv,sbias[h*CC+5]);
        o[6]=fmaf(a67.x,inv,sbias[h*CC+6]); o[7]=fmaf(a67.y,inv,sbias[h*CC+7]);
    }
    __syncthreads();

    // ti/tj: 2048 values (side, hh, nl); nl fast within warp (broadcast W1 row, shg stride 33)
#pragma unroll
    for (int rep = 0; rep < 8; rep++) {
        int o = rep*256 + t;
        int is_tj = o >> 10;
        int hh = (o >> 5) & 31;
        int nl = o & 31;
        float acc = is_tj ? 0.f : sb1[hh];
        const float* wrow = sW1 + hh*64 + is_tj*32;
        const float* hr = shg + nl*33;
#pragma unroll
        for (int d = 0; d < HID; d++) acc = fmaf(hr[d], wrow[d], acc);
        sprod[is_tj*1024 + hh*32 + nl] = acc;
    }
    __syncthreads();

    // pack to half2 by h-pairs and store
    for (int k = t; k < 1024; k += 256) {
        int nl = k & 31;
        int h2 = (k >> 5) & 15;
        int side = k >> 9;
        float lo = sprod[side*1024 + (2*h2)*32 + nl];
        float hi = sprod[side*1024 + (2*h2+1)*32 + nl];
        __half2 v = __floats2half2_rn(lo, hi);
        (side ? d_tjH2 : d_tiH2)[h2*BN + base + j0 + nl] = v;
    }
}

// ---------------- kernel 4: pairwise score, fp16 math ----------------
#define IT 32
__global__ void __launch_bounds__(512, 2) k4_score(const float* __restrict__ w2,
                                                   const float* __restrict__ b2p,
                                                   float* __restrict__ out) {
    __shared__ unsigned stiH[IT*20];   // per row: 16 half2 (64B) + pad, stride 20 u32 (80B)

    int b  = blockIdx.y;
    int i0 = blockIdx.x * IT;
    int t  = threadIdx.x;              // 512 threads, one j each
    int base = b * NN;

    // stage ti rows (half2), coalesced on ii
    {
        int ii = t & 31, h2 = t >> 5;  // t covers 512 = 32 ii x 16 h2
        __half2 v = d_tiH2[h2*BN + base + i0 + ii];
        stiH[ii*20 + h2] = *(unsigned*)&v;
    }

    int j = t;
    float b2v = b2p[0];

    __half2 tj2[16];
#pragma unroll
    for (int k = 0; k < 16; k++) tj2[k] = d_tjH2[k*BN + base + j];

    __half2 w2h[16];
#pragma unroll
    for (int k = 0; k < 16; k++) w2h[k] = __floats2half2_rn(w2[2*k], w2[2*k+1]);

    unsigned mw = d_maskT[(base + j)*NW + (i0 >> 5)];
    float* orow = out + (size_t)(base + i0)*NN + j;
    const __half2 z2 = __floats2half2_rn(0.f, 0.f);
    __syncthreads();

#pragma unroll 4
    for (int ii = 0; ii < IT; ii++) {
        const uint4* tip = (const uint4*)(stiH + ii*20);
        uint4 r0 = tip[0], r1 = tip[1], r2 = tip[2], r3 = tip[3];
        const __half2* ti2 = (const __half2*)&r0;   // r0..r3 contiguous? not guaranteed; handle per-vec
        __half2 acc0 = z2, acc1 = z2, acc2 = z2, acc3 = z2;
        {
            const __half2* p = (const __half2*)&r0;
#pragma unroll
            for (int q = 0; q < 4; q++) {
                __half2 x = __hadd2(p[q], tj2[q]);
                acc0 = __hfma2(__hmax2(x, z2), w2h[q], acc0);
            }
        }
        {
            const __half2* p = (const __half2*)&r1;
#pragma unroll
            for (int q = 0; q < 4; q++) {
                __half2 x = __hadd2(p[q], tj2[4+q]);
                acc1 = __hfma2(__hmax2(x, z2), w2h[4+q], acc1);
            }
        }
        {
            const __half2* p = (const __half2*)&r2;
#pragma unroll
            for (int q = 0; q < 4; q++) {
                __half2 x = __hadd2(p[q], tj2[8+q]);
                acc2 = __hfma2(__hmax2(x, z2), w2h[8+q], acc2);
            }
        }
        {
            const __half2* p = (const __half2*)&r3;
#pragma unroll
            for (int q = 0; q < 4; q++) {
                __half2 x = __hadd2(p[q], tj2[12+q]);
                acc3 = __hfma2(__hmax2(x, z2), w2h[12+q], acc3);
            }
        }
        (void)ti2;
        __half2 s2 = __hadd2(__hadd2(acc0, acc1), __hadd2(acc2, acc3));
        float logit = b2v + __low2float(s2) + __high2float(s2);
        float s = 1.f / (1.f + __expf(-logit));
        bool on = ((mw >> ii) & 1u) && ((i0 + ii) != j);
        orow[ii*NN] = on ? s : 0.f;
    }
}

// ---------------- launcher ----------------
extern "C" void kernel_launch(void* const* d_in, const int* in_sizes, int n_in,
                              void* d_out, int out_size) {
    const float* x       = (const float*)d_in[0];
    const int*   adj     = (const int*)  d_in[1];
    const float* Wp      = (const float*)d_in[2];
    const float* bp      = (const float*)d_in[3];
    const float* Wg      = (const float*)d_in[4];
    const float* att_src = (const float*)d_in[5];
    const float* att_dst = (const float*)d_in[6];
    const float* bias_g  = (const float*)d_in[7];
    const float* W1      = (const float*)d_in[8];
    const float* b1      = (const float*)d_in[9];
    const float* w2      = (const float*)d_in[10];
    const float* b2      = (const float*)d_in[11];
    float* out = (float*)d_out;

    k1_features<<<(BN*4)/128, 128>>>(x, Wp, bp, Wg, att_src, att_dst);
    kT_mask<<<dim3(NN/32, NN/32, BB), dim3(32, 32)>>>(adj);
    k2_attn<<<dim3(NN/JT, BB), 256>>>(bias_g, W1, b1);
    k4_score<<<dim3(NN/IT, BB), 512>>>(w2, b2, out);
}